// round 16
// baseline (speedup 1.0000x reference)
#include <cuda_runtime.h>
#include <cstdint>

#define B_   128
#define L_   336
#define LP   352
#define N_   321
#define E_   128
#define LAT_ 64
#define NE_  (N_ * E_)
#define NL_  (N_ * LAT_)

#define H_SZ    (B_ * N_ * E_)
#define MU_SZ   (B_ * N_ * LAT_)
#define OFF_H   0
#define OFF_HH  (H_SZ)
#define OFF_MU  (2 * H_SZ)
#define OFF_VAR (2 * H_SZ + MU_SZ)

__device__ float g_xp[(size_t)N_ * B_ * LP];   // [n][b][l], zero-padded, tf32-rounded

// ---------------- helpers ----------------
static __device__ __forceinline__ uint32_t s2u(const void* p) {
    uint32_t a;
    asm("{ .reg .u64 t; cvta.to.shared.u64 t, %1; cvt.u32.u64 %0, t; }" : "=r"(a) : "l"(p));
    return a;
}
#define CP16(d, s)      asm volatile("cp.async.cg.shared.global [%0], [%1], 16;" :: "r"(d), "l"(s))
#define CP16Z(d, s, sz) asm volatile("cp.async.cg.shared.global [%0], [%1], 16, %2;" :: "r"(d), "l"(s), "r"(sz))
#define CP_COMMIT() asm volatile("cp.async.commit_group;" ::: "memory")
#define CP_WAIT1()  asm volatile("cp.async.wait_group 1;" ::: "memory")
#define CP_WAIT0()  asm volatile("cp.async.wait_group 0;" ::: "memory")

static __device__ __forceinline__ uint32_t to_tf32(float f) {
    uint32_t u;
    asm("cvt.rna.tf32.f32 %0, %1;" : "=r"(u) : "f"(f));
    return u;
}
static __device__ __forceinline__ void mma_tf32(float c[4],
                                                uint32_t a0, uint32_t a1, uint32_t a2, uint32_t a3,
                                                uint32_t b0, uint32_t b1) {
    asm volatile("mma.sync.aligned.m16n8k8.row.col.f32.tf32.tf32.f32 "
                 "{%0,%1,%2,%3}, {%4,%5,%6,%7}, {%8,%9}, {%0,%1,%2,%3};"
                 : "+f"(c[0]), "+f"(c[1]), "+f"(c[2]), "+f"(c[3])
                 : "r"(a0), "r"(a1), "r"(a2), "r"(a3), "r"(b0), "r"(b1));
}
static __device__ __forceinline__ float sigf(float t) {
    return 1.f / (1.f + __expf(-t));
}

// ---------------- transpose x [B,L,N] -> xp [N,B,LP], tf32-rounded ----------------
// Wide tile: 32 (n) x 128 (l); float4 stores for DRAM write page locality.
__global__ void t1_kernel(const float* __restrict__ x, float* __restrict__ xp) {
    __shared__ float t[128][33];
    const int b = blockIdx.z, n0 = blockIdx.x * 32, l0 = blockIdx.y * 128;
    const int tx = threadIdx.x, ty = threadIdx.y;
    const float* xb = x + (size_t)b * L_ * N_;
#pragma unroll
    for (int i = 0; i < 16; i++) {
        const int ll = ty + 8 * i;
        const int l = l0 + ll, nn = n0 + tx;
        t[ll][tx] = (l < L_ && nn < N_) ? __ldcs(&xb[l * N_ + nn]) : 0.f;
    }
    __syncthreads();
    const int lq = 4 * tx;
    const bool lok = (l0 + lq) < LP;
#pragma unroll
    for (int j = 0; j < 4; j++) {
        const int nn = n0 + ty * 4 + j;
        if (nn < N_ && lok) {
            float4 v;
            v.x = __uint_as_float(to_tf32(t[lq + 0][nn - n0]));
            v.y = __uint_as_float(to_tf32(t[lq + 1][nn - n0]));
            v.z = __uint_as_float(to_tf32(t[lq + 2][nn - n0]));
            v.w = __uint_as_float(to_tf32(t[lq + 3][nn - n0]));
            *(float4*)(xp + (size_t)nn * B_ * LP + b * LP + l0 + lq) = v;
        }
    }
}

// ---------------- fused per-(b-half, channel) kernel ----------------
// Mainloop smem (floats): bufA[2] 64x36 @0/2304 ; bufB[2] 32x128 swz @4608/8704 (end 12800)
// Epilogue smem: stage 64x132 @0 (8448) ; B2 128x64 swz @8448 (end 16640)
#define SA    36
#define SSTG  132
#define NC1   11
#define F_A0  0
#define F_A1  2304
#define F_B0  4608
#define F_B1  8704
#define F_STG 0
#define F_B2  8448
#define SM_BYTES (16640 * 4)

__global__ __launch_bounds__(256, 3)
void fused_kernel(const float* __restrict__ xp, const float* __restrict__ We,
                  const float* __restrict__ be, const float* __restrict__ txg,
                  const float* __restrict__ Wmu, const float* __restrict__ bmu,
                  const float* __restrict__ Wvar, const float* __restrict__ bvar,
                  float* __restrict__ out)
{
    extern __shared__ float sm[];
    const uint32_t sb = s2u(sm);
    const int tid = threadIdx.x, wid = tid >> 5, lane = tid & 31;
    const int g = lane >> 2, tg = lane & 3;
    const int n = blockIdx.y;              // channel (siblings adjacent in x)
    const int b0 = blockIdx.x * 64;        // b-half
    const int m0 = (wid & 1) * 32;         // GEMM1 warp m-base (local row)
    const int n0 = (wid >> 1) * 32;        // GEMM1 warp n-base (e)

    const float* Abase = xp + (size_t)n * B_ * LP + (size_t)b0 * LP;
    const float* Wbase = We + (size_t)n * L_ * E_;

    const int m_a  = tid >> 3;
    const int sg_a = (tid & 7) * 4;
    const int r0b  = tid >> 5;
    const int sg_b = (tid & 31) * 4;
    const int fcb  = sg_b ^ ((r0b & 3) << 3);

    const float* pA = Abase + m_a * LP + sg_a;
    const uint32_t dA[2] = { sb + (uint32_t)(F_A0 + m_a * SA + sg_a) * 4u,
                             sb + (uint32_t)(F_A1 + m_a * SA + sg_a) * 4u };
    const uint32_t dB[2] = { sb + (uint32_t)(F_B0 + r0b * 128 + fcb) * 4u,
                             sb + (uint32_t)(F_B1 + r0b * 128 + fcb) * 4u };

    auto load_chunk = [&](int c, int buf) {
        const float* a = pA + c * 32;
        CP16(dA[buf], a);
        CP16(dA[buf] + 32u * SA * 4u, a + 32 * LP);
        const int lb = c * 32 + r0b;
        const float* bsrc = Wbase + lb * E_ + sg_b;
#pragma unroll
        for (int j = 0; j < 4; j++) {
            const int lg = lb + 8 * j;
            const uint32_t sz = (lg < L_) ? 16u : 0u;
            const float* s = (lg < L_) ? (bsrc + 8 * j * E_) : Wbase;
            CP16Z(dB[buf] + (uint32_t)(8 * j) * 128u * 4u, s, sz);
        }
        CP_COMMIT();
    };

    float acc[2][4][4];
#pragma unroll
    for (int mi = 0; mi < 2; mi++)
#pragma unroll
        for (int ni = 0; ni < 4; ni++)
#pragma unroll
            for (int r = 0; r < 4; r++) acc[mi][ni][r] = 0.f;

    load_chunk(0, 0);
    load_chunk(1, 1);

    const int txg8 = tg << 3;
    int njc[4];
#pragma unroll
    for (int ni = 0; ni < 4; ni++) njc[ni] = (n0 + ni * 8 + g) ^ txg8;

    for (int c = 0; c < NC1; c++) {
        const int buf = c & 1;
        if (c + 1 < NC1) CP_WAIT1(); else CP_WAIT0();
        __syncthreads();
        const float* As = sm + (buf ? F_A1 : F_A0);
        const float* Bs = sm + (buf ? F_B1 : F_B0);
#pragma unroll
        for (int s = 0; s < 4; s++) {
            const int k0 = s * 8;
            uint32_t af[2][4];
#pragma unroll
            for (int mi = 0; mi < 2; mi++) {
                const int r0 = m0 + mi * 16 + g;
                af[mi][0] = __float_as_uint(As[r0 * SA + k0 + tg]);
                af[mi][1] = __float_as_uint(As[(r0 + 8) * SA + k0 + tg]);
                af[mi][2] = __float_as_uint(As[r0 * SA + k0 + tg + 4]);
                af[mi][3] = __float_as_uint(As[(r0 + 8) * SA + k0 + tg + 4]);
            }
            const float* Br0 = Bs + (k0 + tg) * 128;
            const float* Br1 = Bs + (k0 + tg + 4) * 128;
#pragma unroll
            for (int ni = 0; ni < 4; ni++) {
                uint32_t bf0 = to_tf32(Br0[njc[ni]]);
                uint32_t bf1 = to_tf32(Br1[njc[ni]]);
#pragma unroll
                for (int mi = 0; mi < 2; mi++)
                    mma_tf32(acc[mi][ni], af[mi][0], af[mi][1], af[mi][2], af[mi][3], bf0, bf1);
            }
        }
        __syncthreads();
        if (c + 2 < NC1) load_chunk(c + 2, buf);
    }
    __syncthreads();   // all warps done with mainloop B buffers

    // prefetch GEMM2 B (W_mu native [e][j]) into B2, stride 64 + XOR swizzle
    {
        const float* Wsrc = Wmu + (size_t)n * E_ * LAT_;
#pragma unroll
        for (int i = 0; i < 8; i++) {
            int op = tid + i * 256;
            int row = op >> 4, seg = op & 15;
            int fcol = (seg * 4) ^ ((row & 3) << 3);
            uint32_t dst = sb + (uint32_t)(F_B2 + row * 64 + fcol) * 4u;
            CP16(dst, Wsrc + row * LAT_ + seg * 4);
        }
        CP_COMMIT();
    }

    // epilogue 1: h -> gmem (streaming); hh -> gmem (streaming) + stage (tf32)
    float* out_h  = out + OFF_H;
    float* out_hh = out + OFF_HH;
#pragma unroll
    for (int mi = 0; mi < 2; mi++) {
#pragma unroll
        for (int ni = 0; ni < 4; ni++) {
            const int col = n0 + ni * 8 + 2 * tg;
            float2 bv = *(const float2*)(be + n * E_ + col);
#pragma unroll
            for (int half = 0; half < 2; half++) {
                const int lr = m0 + mi * 16 + g + half * 8;
                const int brow = b0 + lr;
                const int o = brow * NE_ + n * E_ + col;
                float2 h;
                h.x = acc[mi][ni][2 * half + 0] + bv.x;
                h.y = acc[mi][ni][2 * half + 1] + bv.y;
                __stcs((float2*)(out_h + o), h);
                float2 t = __ldcs((const float2*)(txg + o));
                float2 hh;
                hh.x = h.x * sigf(t.x);
                hh.y = h.y * sigf(t.y);
                __stcs((float2*)(out_hh + o), hh);
                *(float2*)(sm + F_STG + lr * SSTG + col) =
                    make_float2(__uint_as_float(to_tf32(hh.x)), __uint_as_float(to_tf32(hh.y)));
            }
        }
    }
    CP_WAIT0();
    __syncthreads();

    // GEMM2: pass 0 = mu (W_mu), pass 1 = var (W_var); j in [0,64)
    const int m2 = (wid & 1) * 32;
    const int nt = (wid >> 1) * 16;
    int jnc[2];
#pragma unroll
    for (int ni = 0; ni < 2; ni++) jnc[ni] = (nt + ni * 8 + g) ^ txg8;

    const float* A2 = sm + F_STG;
    const float* B2 = sm + F_B2;

#pragma unroll
    for (int p = 0; p < 2; p++) {
        if (p == 1) {
            __syncthreads();
            const float* Wsrc = Wvar + (size_t)n * E_ * LAT_;
#pragma unroll
            for (int i = 0; i < 8; i++) {
                int op = tid + i * 256;
                int row = op >> 4, seg = op & 15;
                int fcol = (seg * 4) ^ ((row & 3) << 3);
                uint32_t dst = sb + (uint32_t)(F_B2 + row * 64 + fcol) * 4u;
                CP16(dst, Wsrc + row * LAT_ + seg * 4);
            }
            CP_COMMIT();
            CP_WAIT0();
            __syncthreads();
        }

        float acc2[2][2][4];
#pragma unroll
        for (int mi = 0; mi < 2; mi++)
#pragma unroll
            for (int ni = 0; ni < 2; ni++)
#pragma unroll
                for (int r = 0; r < 4; r++) acc2[mi][ni][r] = 0.f;

#pragma unroll
        for (int s = 0; s < 16; s++) {
            const int k0 = s * 8;
            uint32_t af[2][4];
#pragma unroll
            for (int mi = 0; mi < 2; mi++) {
                const int r0 = m2 + mi * 16 + g;
                af[mi][0] = __float_as_uint(A2[r0 * SSTG + k0 + tg]);
                af[mi][1] = __float_as_uint(A2[(r0 + 8) * SSTG + k0 + tg]);
                af[mi][2] = __float_as_uint(A2[r0 * SSTG + k0 + tg + 4]);
                af[mi][3] = __float_as_uint(A2[(r0 + 8) * SSTG + k0 + tg + 4]);
            }
            const float* Br0 = B2 + (k0 + tg) * 64;
            const float* Br1 = B2 + (k0 + tg + 4) * 64;
#pragma unroll
            for (int ni = 0; ni < 2; ni++) {
                uint32_t bf0 = to_tf32(Br0[jnc[ni]]);
                uint32_t bf1 = to_tf32(Br1[jnc[ni]]);
#pragma unroll
                for (int mi = 0; mi < 2; mi++)
                    mma_tf32(acc2[mi][ni], af[mi][0], af[mi][1], af[mi][2], af[mi][3], bf0, bf1);
            }
        }

        const float* bp = (p ? bvar : bmu) + n * LAT_;
        float* outp = out + (p ? OFF_VAR : OFF_MU);
#pragma unroll
        for (int mi = 0; mi < 2; mi++) {
#pragma unroll
            for (int ni = 0; ni < 2; ni++) {
                const int col = nt + ni * 8 + 2 * tg;
                float2 bv = *(const float2*)(bp + col);
#pragma unroll
                for (int half = 0; half < 2; half++) {
                    const int brow = b0 + m2 + mi * 16 + g + half * 8;
                    float2 v;
                    v.x = acc2[mi][ni][2 * half + 0] + bv.x;
                    v.y = acc2[mi][ni][2 * half + 1] + bv.y;
                    __stcs((float2*)(outp + brow * NL_ + n * LAT_ + col), v);
                }
            }
        }
    }
}

// ---------------- launch ----------------
extern "C" void kernel_launch(void* const* d_in, const int* in_sizes, int n_in,
                              void* d_out, int out_size) {
    const float* x    = (const float*)d_in[0];
    const float* txg  = (const float*)d_in[1];
    const float* We   = (const float*)d_in[2];
    const float* be   = (const float*)d_in[3];
    const float* Wmu  = (const float*)d_in[4];
    const float* bmu  = (const float*)d_in[5];
    const float* Wvar = (const float*)d_in[6];
    const float* bvar = (const float*)d_in[7];
    float* out = (float*)d_out;

    float* xp;
    cudaGetSymbolAddress((void**)&xp, g_xp);

    cudaFuncSetAttribute(fused_kernel, cudaFuncAttributeMaxDynamicSharedMemorySize, SM_BYTES);

    t1_kernel<<<dim3(11, 3, B_), dim3(32, 8)>>>(x, xp);
    fused_kernel<<<dim3(2, N_), 256, SM_BYTES>>>(xp, We, be, txg, Wmu, bmu, Wvar, bvar, out);
}

// round 17
// speedup vs baseline: 1.1855x; 1.1855x over previous
#include <cuda_runtime.h>
#include <cstdint>

#define B_   128
#define L_   336
#define LP   352
#define N_   321
#define E_   128
#define LAT_ 64
#define NE_  (N_ * E_)
#define NL_  (N_ * LAT_)

#define H_SZ    (B_ * N_ * E_)
#define MU_SZ   (B_ * N_ * LAT_)
#define OFF_H   0
#define OFF_HH  (H_SZ)
#define OFF_MU  (2 * H_SZ)
#define OFF_VAR (2 * H_SZ + MU_SZ)

__device__ float g_xp[(size_t)N_ * B_ * LP];   // [n][b][l], zero-padded, tf32-rounded

// ---------------- helpers ----------------
static __device__ __forceinline__ uint32_t s2u(const void* p) {
    uint32_t a;
    asm("{ .reg .u64 t; cvta.to.shared.u64 t, %1; cvt.u32.u64 %0, t; }" : "=r"(a) : "l"(p));
    return a;
}
#define CP16(d, s)      asm volatile("cp.async.cg.shared.global [%0], [%1], 16;" :: "r"(d), "l"(s))
#define CP16Z(d, s, sz) asm volatile("cp.async.cg.shared.global [%0], [%1], 16, %2;" :: "r"(d), "l"(s), "r"(sz))
#define CP_COMMIT() asm volatile("cp.async.commit_group;" ::: "memory")
#define CP_WAIT1()  asm volatile("cp.async.wait_group 1;" ::: "memory")
#define CP_WAIT0()  asm volatile("cp.async.wait_group 0;" ::: "memory")

static __device__ __forceinline__ uint32_t to_tf32(float f) {
    uint32_t u;
    asm("cvt.rna.tf32.f32 %0, %1;" : "=r"(u) : "f"(f));
    return u;
}
static __device__ __forceinline__ void mma_tf32(float c[4],
                                                uint32_t a0, uint32_t a1, uint32_t a2, uint32_t a3,
                                                uint32_t b0, uint32_t b1) {
    asm volatile("mma.sync.aligned.m16n8k8.row.col.f32.tf32.tf32.f32 "
                 "{%0,%1,%2,%3}, {%4,%5,%6,%7}, {%8,%9}, {%0,%1,%2,%3};"
                 : "+f"(c[0]), "+f"(c[1]), "+f"(c[2]), "+f"(c[3])
                 : "r"(a0), "r"(a1), "r"(a2), "r"(a3), "r"(b0), "r"(b1));
}
static __device__ __forceinline__ float sigf(float t) {
    return 1.f / (1.f + __expf(-t));
}

// ---------------- transpose x [B,L,N] -> xp [N,B,LP], tf32-rounded ----------------
// Wide tile: 32 (n) x 128 (l); float4 stores for DRAM write page locality.
__global__ void t1_kernel(const float* __restrict__ x, float* __restrict__ xp) {
    __shared__ float t[128][33];
    const int b = blockIdx.z, n0 = blockIdx.x * 32, l0 = blockIdx.y * 128;
    const int tx = threadIdx.x, ty = threadIdx.y;
    const float* xb = x + (size_t)b * L_ * N_;
#pragma unroll
    for (int i = 0; i < 16; i++) {
        const int ll = ty + 8 * i;
        const int l = l0 + ll, nn = n0 + tx;
        t[ll][tx] = (l < L_ && nn < N_) ? xb[l * N_ + nn] : 0.f;
    }
    __syncthreads();
    const int lq = 4 * tx;
    const bool lok = (l0 + lq) < LP;
#pragma unroll
    for (int j = 0; j < 4; j++) {
        const int nn = n0 + ty * 4 + j;
        if (nn < N_ && lok) {
            float4 v;
            v.x = __uint_as_float(to_tf32(t[lq + 0][nn - n0]));
            v.y = __uint_as_float(to_tf32(t[lq + 1][nn - n0]));
            v.z = __uint_as_float(to_tf32(t[lq + 2][nn - n0]));
            v.w = __uint_as_float(to_tf32(t[lq + 3][nn - n0]));
            *(float4*)(xp + (size_t)nn * B_ * LP + b * LP + l0 + lq) = v;
        }
    }
}

// ---------------- fused per-(b-half, channel) kernel ----------------
// Triple-buffered mainloop (loads issued BEFORE MMA, 1 barrier/chunk):
//   bufA[3] 64x36 @0/2304/4608 ; bufB[3] 32x128 swz @6912/11008/15104 (end 19200)
// Epilogue smem: stage 64x132 @0 (8448) ; B2 128x64 swz @8448 (end 16640)
#define SA    36
#define SSTG  132
#define NC1   11
#define F_STG 0
#define F_B2  8448
#define SM_BYTES (19200 * 4)

__global__ __launch_bounds__(256, 3)
void fused_kernel(const float* __restrict__ xp, const float* __restrict__ We,
                  const float* __restrict__ be, const float* __restrict__ txg,
                  const float* __restrict__ Wmu, const float* __restrict__ bmu,
                  const float* __restrict__ Wvar, const float* __restrict__ bvar,
                  float* __restrict__ out)
{
    extern __shared__ float sm[];
    const uint32_t sb = s2u(sm);
    const int tid = threadIdx.x, wid = tid >> 5, lane = tid & 31;
    const int g = lane >> 2, tg = lane & 3;
    const int n = blockIdx.y;              // channel (siblings adjacent in x)
    const int b0 = blockIdx.x * 64;        // b-half
    const int m0 = (wid & 1) * 32;         // GEMM1 warp m-base (local row)
    const int n0 = (wid >> 1) * 32;        // GEMM1 warp n-base (e)

    const float* Abase = xp + (size_t)n * B_ * LP + (size_t)b0 * LP;
    const float* Wbase = We + (size_t)n * L_ * E_;

    // per-thread load geometry (compile-time buffer bases fold under unroll)
    const int m_a  = tid >> 3;
    const int sg_a = (tid & 7) * 4;
    const int r0b  = tid >> 5;
    const int sg_b = (tid & 31) * 4;
    const int fcb  = sg_b ^ ((r0b & 3) << 3);
    const uint32_t aoff4 = (uint32_t)(m_a * SA + sg_a) * 4u;
    const uint32_t boff4 = (uint32_t)(r0b * 128 + fcb) * 4u;
    const float* pA = Abase + m_a * LP + sg_a;

    auto load_chunk = [&](int c, int FAbuf, int FBbuf) {
        const float* a = pA + c * 32;
        const uint32_t da = sb + (uint32_t)FAbuf * 4u + aoff4;
        CP16(da, a);
        CP16(da + 32u * SA * 4u, a + 32 * LP);
        const int lb = c * 32 + r0b;
        const float* bsrc = Wbase + lb * E_ + sg_b;
        const uint32_t db = sb + (uint32_t)FBbuf * 4u + boff4;
#pragma unroll
        for (int j = 0; j < 4; j++) {
            const int lg = lb + 8 * j;
            const uint32_t sz = (lg < L_) ? 16u : 0u;
            const float* s = (lg < L_) ? (bsrc + 8 * j * E_) : Wbase;
            CP16Z(db + (uint32_t)(8 * j) * 128u * 4u, s, sz);
        }
        CP_COMMIT();
    };

    float acc[2][4][4];
#pragma unroll
    for (int mi = 0; mi < 2; mi++)
#pragma unroll
        for (int ni = 0; ni < 4; ni++)
#pragma unroll
            for (int r = 0; r < 4; r++) acc[mi][ni][r] = 0.f;

    const int FAc[3] = {0, 2304, 4608};
    const int FBc[3] = {6912, 11008, 15104};

    load_chunk(0, FAc[0], FBc[0]);
    load_chunk(1, FAc[1], FBc[1]);

    const int txg8 = tg << 3;
    int njc[4];
#pragma unroll
    for (int ni = 0; ni < 4; ni++) njc[ni] = (n0 + ni * 8 + g) ^ txg8;

#pragma unroll
    for (int c = 0; c < NC1; c++) {
        const int buf = c % 3;
        if (c + 1 < NC1) CP_WAIT1(); else CP_WAIT0();
        __syncthreads();                     // single barrier per chunk
        if (c + 2 < NC1) load_chunk(c + 2, FAc[(c + 2) % 3], FBc[(c + 2) % 3]);
        const float* As = sm + FAc[buf];
        const float* Bs = sm + FBc[buf];
#pragma unroll
        for (int s = 0; s < 4; s++) {
            const int k0 = s * 8;
            uint32_t af[2][4];
#pragma unroll
            for (int mi = 0; mi < 2; mi++) {
                const int r0 = m0 + mi * 16 + g;
                af[mi][0] = __float_as_uint(As[r0 * SA + k0 + tg]);
                af[mi][1] = __float_as_uint(As[(r0 + 8) * SA + k0 + tg]);
                af[mi][2] = __float_as_uint(As[r0 * SA + k0 + tg + 4]);
                af[mi][3] = __float_as_uint(As[(r0 + 8) * SA + k0 + tg + 4]);
            }
            const float* Br0 = Bs + (k0 + tg) * 128;
            const float* Br1 = Bs + (k0 + tg + 4) * 128;
#pragma unroll
            for (int ni = 0; ni < 4; ni++) {
                uint32_t bf0 = to_tf32(Br0[njc[ni]]);
                uint32_t bf1 = to_tf32(Br1[njc[ni]]);
#pragma unroll
                for (int mi = 0; mi < 2; mi++)
                    mma_tf32(acc[mi][ni], af[mi][0], af[mi][1], af[mi][2], af[mi][3], bf0, bf1);
            }
        }
    }
    __syncthreads();   // all warps done with mainloop buffers before stage reuse

    // prefetch GEMM2 B (W_mu native [e][j]) into B2, stride 64 + XOR swizzle
    {
        const float* Wsrc = Wmu + (size_t)n * E_ * LAT_;
#pragma unroll
        for (int i = 0; i < 8; i++) {
            int op = tid + i * 256;
            int row = op >> 4, seg = op & 15;
            int fcol = (seg * 4) ^ ((row & 3) << 3);
            uint32_t dst = sb + (uint32_t)(F_B2 + row * 64 + fcol) * 4u;
            CP16(dst, Wsrc + row * LAT_ + seg * 4);
        }
        CP_COMMIT();
    }

    // epilogue 1: h = acc + bias -> gmem; hh -> gmem (fp32) + stage (tf32-rounded)
    float* out_h  = out + OFF_H;
    float* out_hh = out + OFF_HH;
#pragma unroll
    for (int mi = 0; mi < 2; mi++) {
#pragma unroll
        for (int ni = 0; ni < 4; ni++) {
            const int col = n0 + ni * 8 + 2 * tg;
            float2 bv = *(const float2*)(be + n * E_ + col);
#pragma unroll
            for (int half = 0; half < 2; half++) {
                const int lr = m0 + mi * 16 + g + half * 8;
                const int brow = b0 + lr;
                const int o = brow * NE_ + n * E_ + col;
                float2 h;
                h.x = acc[mi][ni][2 * half + 0] + bv.x;
                h.y = acc[mi][ni][2 * half + 1] + bv.y;
                *(float2*)(out_h + o) = h;
                float2 t = *(const float2*)(txg + o);
                float2 hh;
                hh.x = h.x * sigf(t.x);
                hh.y = h.y * sigf(t.y);
                *(float2*)(out_hh + o) = hh;
                *(float2*)(sm + F_STG + lr * SSTG + col) =
                    make_float2(__uint_as_float(to_tf32(hh.x)), __uint_as_float(to_tf32(hh.y)));
            }
        }
    }
    CP_WAIT0();
    __syncthreads();

    // GEMM2: pass 0 = mu (W_mu), pass 1 = var (W_var); j in [0,64)
    const int m2 = (wid & 1) * 32;
    const int nt = (wid >> 1) * 16;
    int jnc[2];
#pragma unroll
    for (int ni = 0; ni < 2; ni++) jnc[ni] = (nt + ni * 8 + g) ^ txg8;

    const float* A2 = sm + F_STG;
    const float* B2 = sm + F_B2;

#pragma unroll
    for (int p = 0; p < 2; p++) {
        if (p == 1) {
            __syncthreads();
            const float* Wsrc = Wvar + (size_t)n * E_ * LAT_;
#pragma unroll
            for (int i = 0; i < 8; i++) {
                int op = tid + i * 256;
                int row = op >> 4, seg = op & 15;
                int fcol = (seg * 4) ^ ((row & 3) << 3);
                uint32_t dst = sb + (uint32_t)(F_B2 + row * 64 + fcol) * 4u;
                CP16(dst, Wsrc + row * LAT_ + seg * 4);
            }
            CP_COMMIT();
            CP_WAIT0();
            __syncthreads();
        }

        float acc2[2][2][4];
#pragma unroll
        for (int mi = 0; mi < 2; mi++)
#pragma unroll
            for (int ni = 0; ni < 2; ni++)
#pragma unroll
                for (int r = 0; r < 4; r++) acc2[mi][ni][r] = 0.f;

#pragma unroll
        for (int s = 0; s < 16; s++) {
            const int k0 = s * 8;
            uint32_t af[2][4];
#pragma unroll
            for (int mi = 0; mi < 2; mi++) {
                const int r0 = m2 + mi * 16 + g;
                af[mi][0] = __float_as_uint(A2[r0 * SSTG + k0 + tg]);
                af[mi][1] = __float_as_uint(A2[(r0 + 8) * SSTG + k0 + tg]);
                af[mi][2] = __float_as_uint(A2[r0 * SSTG + k0 + tg + 4]);
                af[mi][3] = __float_as_uint(A2[(r0 + 8) * SSTG + k0 + tg + 4]);
            }
            const float* Br0 = B2 + (k0 + tg) * 64;
            const float* Br1 = B2 + (k0 + tg + 4) * 64;
#pragma unroll
            for (int ni = 0; ni < 2; ni++) {
                uint32_t bf0 = to_tf32(Br0[jnc[ni]]);
                uint32_t bf1 = to_tf32(Br1[jnc[ni]]);
#pragma unroll
                for (int mi = 0; mi < 2; mi++)
                    mma_tf32(acc2[mi][ni], af[mi][0], af[mi][1], af[mi][2], af[mi][3], bf0, bf1);
            }
        }

        const float* bp = (p ? bvar : bmu) + n * LAT_;
        float* outp = out + (p ? OFF_VAR : OFF_MU);
#pragma unroll
        for (int mi = 0; mi < 2; mi++) {
#pragma unroll
            for (int ni = 0; ni < 2; ni++) {
                const int col = nt + ni * 8 + 2 * tg;
                float2 bv = *(const float2*)(bp + col);
#pragma unroll
                for (int half = 0; half < 2; half++) {
                    const int brow = b0 + m2 + mi * 16 + g + half * 8;
                    float2 v;
                    v.x = acc2[mi][ni][2 * half + 0] + bv.x;
                    v.y = acc2[mi][ni][2 * half + 1] + bv.y;
                    *(float2*)(outp + brow * NL_ + n * LAT_ + col) = v;
                }
            }
        }
    }
}

// ---------------- launch ----------------
extern "C" void kernel_launch(void* const* d_in, const int* in_sizes, int n_in,
                              void* d_out, int out_size) {
    const float* x    = (const float*)d_in[0];
    const float* txg  = (const float*)d_in[1];
    const float* We   = (const float*)d_in[2];
    const float* be   = (const float*)d_in[3];
    const float* Wmu  = (const float*)d_in[4];
    const float* bmu  = (const float*)d_in[5];
    const float* Wvar = (const float*)d_in[6];
    const float* bvar = (const float*)d_in[7];
    float* out = (float*)d_out;

    float* xp;
    cudaGetSymbolAddress((void**)&xp, g_xp);

    cudaFuncSetAttribute(fused_kernel, cudaFuncAttributeMaxDynamicSharedMemorySize, SM_BYTES);

    t1_kernel<<<dim3(11, 3, B_), dim3(32, 8)>>>(x, xp);
    fused_kernel<<<dim3(2, N_), 256, SM_BYTES>>>(xp, We, be, txg, Wmu, bmu, Wvar, bvar, out);
}